// round 16
// baseline (speedup 1.0000x reference)
#include <cuda_runtime.h>
#include <cuda_fp16.h>

typedef unsigned long long ull;

#define E_CNT 1600000
#define N_CNT 100000
#define NGRAPH 64
#define NB_SCAN ((N_CNT + 1023) / 1024)   // 98

// ---------------- device scratch ----------------
__device__ alignas(16) unsigned g_portWh[65536 * 32];  // half2[32] per port (incl b1)
__device__ alignas(16) unsigned g_flagsWh[256 * 32];   // half2[32] per flag
__device__ alignas(16) unsigned g_awh[(size_t)E_CNT * 32];  // per-edge h_pre half2, CSR order (205MB)
__device__ float g_invdeg[N_CNT];
__device__ alignas(16) float g_md[N_CNT * 64];
__device__ alignas(16) float g_x[N_CNT * 64];          // x2 fp32 (pass-1 output)
__device__ alignas(16) unsigned g_xh[N_CNT * 32];      // x1 as half2
__device__ alignas(16) unsigned g_xh2[N_CNT * 32];     // x2 as half2
__device__ float g_meanacc[NGRAPH * 64];
__device__ unsigned g_maxacc[NGRAPH * 64];
__device__ float g_gcnt[NGRAPH];
__device__ int g_nctr;                  // work-stealing cursor for k_gather
// CSR
__device__ int g_icnt[N_CNT];
__device__ int g_ofs[N_CNT + 1];
__device__ int g_wr[N_CNT];
__device__ unsigned g_state[NB_SCAN];
__device__ int g_pos[E_CNT];            // natural edge -> CSR slot
__device__ int g_row[E_CNT];            // CSR slot -> src node

// ---------------- packed f32x2 helpers ----------------
__device__ __forceinline__ ull pack2(float x, float y) {
    ull r; asm("mov.b64 %0,{%1,%2};" : "=l"(r) : "f"(x), "f"(y)); return r;
}
__device__ __forceinline__ ull packdup(float x) {
    ull r; asm("mov.b64 %0,{%1,%1};" : "=l"(r) : "f"(x)); return r;
}
__device__ __forceinline__ void unpack2(ull v, float& x, float& y) {
    asm("mov.b64 {%0,%1},%2;" : "=f"(x), "=f"(y) : "l"(v));
}
__device__ __forceinline__ ull fma2(ull a, ull b, ull c) {
    asm("fma.rn.f32x2 %0,%1,%2,%0;" : "+l"(c) : "l"(a), "l"(b)); return c;
}
__device__ __forceinline__ ull fma2s(float s, ull b, ull c) {
    return fma2(packdup(s), b, c);
}
__device__ __forceinline__ ull add2(ull a, ull b) {
    ull d; asm("add.rn.f32x2 %0,%1,%2;" : "=l"(d) : "l"(a), "l"(b)); return d;
}
__device__ __forceinline__ ull mul2(ull a, ull b) {
    ull d; asm("mul.rn.f32x2 %0,%1,%2;" : "=l"(d) : "l"(a), "l"(b)); return d;
}
__device__ __forceinline__ void red4f(float* p, float a, float b, float c, float d) {
    asm volatile("red.global.add.v4.f32 [%0],{%1,%2,%3,%4};"
                 :: "l"(p), "f"(a), "f"(b), "f"(c), "f"(d) : "memory");
}
__device__ __forceinline__ unsigned fkey(float f) {
    unsigned u = __float_as_uint(f);
    return (u & 0x80000000u) ? ~u : (u | 0x80000000u);
}

// ---------------- K0: prep = portW + flagsW + degree count ----------------
#define DEG_BLKS ((E_CNT / 4 + 255) / 256)
__global__ void __launch_bounds__(256) k_prep(const float* __restrict__ embp,
                                              const float* __restrict__ embf,
                                              const float* __restrict__ W1,
                                              const float* __restrict__ b1,
                                              const int* __restrict__ ei) {
    const int b = blockIdx.x;
    if (b < 1024) {
        __shared__ alignas(16) float Wp[16 * 64];
        __shared__ alignas(16) float b1s[64];
        for (int i = threadIdx.x; i < 16 * 64; i += 256) Wp[i] = W1[16 * 64 + i];
        if (threadIdx.x < 64) b1s[threadIdx.x] = b1[threadIdx.x];
        __syncthreads();
        const int wid = threadIdx.x >> 5, L = threadIdx.x & 31;
        for (int p = b * 8 + wid; p < 65536; p += 8192) {
            float a = (L < 16) ? embp[p * 16 + L] : 0.f;
            ull acc = *(const ull*)(b1s + 2 * L);
#pragma unroll
            for (int k = 0; k < 16; k++)
                acc = fma2s(__shfl_sync(0xffffffffu, a, k), *(const ull*)(Wp + k * 64 + 2 * L), acc);
            float x, y; unpack2(acc, x, y);
            __half2 h = __floats2half2_rn(x, y);
            g_portWh[p * 32 + L] = *(unsigned*)&h;
        }
    } else if (b < 1056) {
        const int idx = (b - 1024) * 256 + threadIdx.x;  // [0, 8192)
        const int r = idx >> 5, jp = idx & 31;
        const float e0 = embf[r * 2], e1 = embf[r * 2 + 1];
        const float x = e0 * W1[32 * 64 + 2 * jp] + e1 * W1[33 * 64 + 2 * jp];
        const float y = e0 * W1[32 * 64 + 2 * jp + 1] + e1 * W1[33 * 64 + 2 * jp + 1];
        __half2 h = __floats2half2_rn(x, y);
        g_flagsWh[idx] = *(unsigned*)&h;
    } else {
        const int i = (b - 1056) * 256 + threadIdx.x;
        if (i < E_CNT / 4) {
            int4 c = *(const int4*)(ei + E_CNT + i * 4);
            atomicAdd(g_icnt + c.x, 1);
            atomicAdd(g_icnt + c.y, 1);
            atomicAdd(g_icnt + c.z, 1);
            atomicAdd(g_icnt + c.w, 1);
        }
    }
}

// ---------------- K-scan: single-pass decoupled-lookback prefix scan ----------------
__global__ void __launch_bounds__(1024) k_scan(void) {
    __shared__ int s[1024];
    __shared__ int s_base;
    const int b = blockIdx.x, t = threadIdx.x;
    const int idx = b * 1024 + t;
    const int v = (idx < N_CNT) ? g_icnt[idx] : 0;
    s[t] = v;
    __syncthreads();
#pragma unroll
    for (int d2 = 1; d2 < 1024; d2 <<= 1) {
        int tmp = (t >= d2) ? s[t - d2] : 0;
        __syncthreads();
        s[t] += tmp;
        __syncthreads();
    }
    const int incl = s[t];
    const int total = s[1023];
    if (t == 0) {
        if (b == 0) {
            atomicExch(&g_state[0], (2u << 30) | (unsigned)total);
            s_base = 0;
        } else {
            atomicExch(&g_state[b], (1u << 30) | (unsigned)total);
            int excl = 0, j = b - 1;
            for (;;) {
                unsigned q = atomicAdd(&g_state[j], 0u);
                unsigned st = q >> 30;
                if (st == 0u) continue;
                excl += (int)(q & 0x3FFFFFFFu);
                if (st == 2u) break;
                j--;
            }
            __threadfence();
            atomicExch(&g_state[b], (2u << 30) | (unsigned)(excl + total));
            s_base = excl;
        }
    }
    __syncthreads();
    const int o = s_base + incl - v;
    if (idx < N_CNT) { g_ofs[idx] = o; g_wr[idx] = o; }
    if (idx == N_CNT - 1) g_ofs[N_CNT] = s_base + incl;
}

// ---------------- K-fill: CSR fill -> pos map + row ----------------
__global__ void k_fill(const int* __restrict__ ei) {
    int e = blockIdx.x * blockDim.x + threadIdx.x;
    if (e < E_CNT) {
        int col = ei[E_CNT + e];
        int p = atomicAdd(g_wr + col, 1);
        g_pos[e] = p;
        g_row[p] = ei[e];
    }
}

// ---------------- K-eW: edge-major layer-1, scatter to CSR slot as half2 -------
// warp per edge (strided); lane L owns dims 2L,2L+1; shfl-form attr term
#define EW_BLKS 592   // 148 * 4
__global__ void __launch_bounds__(256, 4) k_eW(
    const float* __restrict__ eattr, const int* __restrict__ ports,
    const int* __restrict__ flags, const float* __restrict__ W1) {
    const int wid = threadIdx.x >> 5, L = threadIdx.x & 31;
    const int l16 = L & 15;
    ull Wr[16];
#pragma unroll
    for (int k = 0; k < 16; k++) Wr[k] = *(const ull*)(W1 + k * 64 + 2 * L);
    const int w0 = blockIdx.x * 8 + wid;
    const int nw = EW_BLKS * 8;     // 4736 warps
    for (int e = w0; e < E_CNT; e += nw) {
        const float a = eattr[(size_t)e * 16 + l16];
        const int port = ports[e];
        const int flag = flags[e];
        const int p = g_pos[e];
        ull acc0 = 0ull, acc1 = 0ull;
#pragma unroll
        for (int k = 0; k < 16; k += 2) {
            acc0 = fma2s(__shfl_sync(0xffffffffu, a, k, 16), Wr[k], acc0);
            acc1 = fma2s(__shfl_sync(0xffffffffu, a, k + 1, 16), Wr[k + 1], acc1);
        }
        const unsigned pw = g_portWh[port * 32 + L];
        const unsigned fw = g_flagsWh[flag * 32 + L];
        const float2 pwf = __half22float2(*(const __half2*)&pw);
        const float2 fwf = __half22float2(*(const __half2*)&fw);
        float x, y; unpack2(add2(acc0, acc1), x, y);
        __half2 h = __floats2half2_rn(x + pwf.x + fwf.x, y + pwf.y + fwf.y);
        g_awh[(size_t)p * 32 + L] = *(unsigned*)&h;
    }
}

// ---------------- K1: gather (sequential awh stream) + node W2 GEMM ----------------
#define GATHER_BLKS 592   // 148 * 4
__global__ void __launch_bounds__(256, 4) k_gather(
    const float* __restrict__ W2, const float* __restrict__ b1,
    const float* __restrict__ b2) {
    __shared__ alignas(16) float4 W2p[1024];
    __shared__ alignas(16) float b1s[64];
    __shared__ alignas(16) float b2s[64];
    for (int idx = threadIdx.x; idx < 1024; idx += 256) {
        const int kk = idx >> 5, LL = idx & 31;
        W2p[idx] = make_float4(W2[(2 * kk) * 64 + 2 * LL], W2[(2 * kk) * 64 + 2 * LL + 1],
                               W2[(2 * kk + 1) * 64 + 2 * LL], W2[(2 * kk + 1) * 64 + 2 * LL + 1]);
    }
    if (threadIdx.x < 64) { b1s[threadIdx.x] = b1[threadIdx.x]; b2s[threadIdx.x] = b2[threadIdx.x]; }
    __syncthreads();
    const int L = threadIdx.x & 31;

    int n0 = 0;
    if (L == 0) n0 = atomicAdd(&g_nctr, 4);
    n0 = __shfl_sync(0xffffffffu, n0, 0);
    while (n0 < N_CNT) {
        const int nlim = (n0 + 4 < N_CNT) ? n0 + 4 : N_CNT;
#pragma unroll 1
        for (int n = n0; n < nlim; n++) {
            const int beg = g_ofs[n], end = g_ofs[n + 1];
            const int deg = end - beg;
            ull hp = 0ull, hs = 0ull;
#pragma unroll 4
            for (int i = beg; i < end; i++) {
                const unsigned aw = g_awh[(size_t)i * 32 + L];   // sequential stream
                const float2 f = __half22float2(*(const __half2*)&aw);
                hp = add2(hp, pack2(f.x, f.y));
                hs = add2(hs, pack2(fmaxf(f.x, 0.f), fmaxf(f.y, 0.f)));
            }
            const float cnt = (float)deg;
            const float inv = 1.f / fmaxf(cnt, 1.f);
            const float c = 1.f - cnt * inv;
            float q0, q1, s0, s1;
            unpack2(hp, q0, q1);
            unpack2(hs, s0, s1);
            const ull hh = pack2(s0 + fmaxf(q0 * inv + b1s[2 * L] * c, 0.f),
                                 s1 + fmaxf(q1 * inv + b1s[2 * L + 1] * c, 0.f));
            const float d = cnt + 1.f;
            ull m0 = pack2(b2s[2 * L] * d, b2s[2 * L + 1] * d);
            ull m1 = 0ull;
#pragma unroll
            for (int kk = 0; kk < 32; kk += 2) {
                const ull t0 = __shfl_sync(0xffffffffu, hh, kk);
                const ull t1 = __shfl_sync(0xffffffffu, hh, kk + 1);
                float x0, x1, x2, x3;
                unpack2(t0, x0, x1);
                unpack2(t1, x2, x3);
                const float4 w0 = W2p[kk * 32 + L];
                const float4 w1 = W2p[(kk + 1) * 32 + L];
                m0 = fma2s(x0, pack2(w0.x, w0.y), m0);
                m0 = fma2s(x1, pack2(w0.z, w0.w), m0);
                m1 = fma2s(x2, pack2(w1.x, w1.y), m1);
                m1 = fma2s(x3, pack2(w1.z, w1.w), m1);
            }
            const ull m = add2(m0, m1);
            const float invd = 1.f / d;
            *(ull*)(g_md + n * 64 + 2 * L) = m;
            float xv0, xv1;
            unpack2(mul2(m, packdup(invd)), xv0, xv1);
            __half2 xh = __floats2half2_rn(xv0, xv1);
            g_xh[n * 32 + L] = *(unsigned*)&xh;
            if (L == 0) g_invdeg[n] = invd;
        }
        if (L == 0) n0 = atomicAdd(&g_nctr, 4);
        n0 = __shfl_sync(0xffffffffu, n0, 0);
    }
}

// ---------------- half2-pair load: dims 4l..4l+3 of node row ----------------
__device__ __forceinline__ float4 ldxh(const unsigned* __restrict__ xh, int row, int l) {
    const ull hv = *(const ull*)(xh + row * 32 + 2 * l);
    const unsigned h0 = (unsigned)hv, h1 = (unsigned)(hv >> 32);
    const float2 f0 = __half22float2(*(const __half2*)&h0);
    const float2 f1 = __half22float2(*(const __half2*)&h1);
    return make_float4(f0.x, f0.y, f1.x, f1.y);
}

// ---------------- K3: SpMM pass 1: x2 = (md*(1+invd) + Σ x1h[row]) * invd -----
__global__ void __launch_bounds__(256) k_spmm1(void) {
    const int wid = threadIdx.x >> 5, L = threadIdx.x & 31;
    const int h = L >> 4, l = L & 15;
    const int n = (blockIdx.x * 8 + wid) * 2 + h;
    if (n >= N_CNT) return;
    const int beg = g_ofs[n], end = g_ofs[n + 1];
    const float invd = g_invdeg[n];
    const float4 m = *(const float4*)(g_md + n * 64 + 4 * l);
    const float c = 1.f + invd;
    float4 acc = make_float4(m.x * c, m.y * c, m.z * c, m.w * c);
#pragma unroll 8
    for (int i = beg; i < end; i++) {
        const int row = g_row[i];
        const float4 v = ldxh(g_xh, row, l);
        acc.x += v.x; acc.y += v.y; acc.z += v.z; acc.w += v.w;
    }
    acc.x *= invd; acc.y *= invd; acc.z *= invd; acc.w *= invd;
    *(float4*)(g_x + n * 64 + 4 * l) = acc;
    __half2 ha = __floats2half2_rn(acc.x, acc.y);
    __half2 hb = __floats2half2_rn(acc.z, acc.w);
    ull hv = ((ull)(*(unsigned*)&hb) << 32) | (*(unsigned*)&ha);
    *(ull*)(g_xh2 + n * 32 + 2 * l) = hv;
}

// ---------------- K4: SpMM pass 2 fused with pooling ----------------
__global__ void __launch_bounds__(256) k_spmm_pool(const int* __restrict__ batch) {
    const int wid = threadIdx.x >> 5, L = threadIdx.x & 31;
    const int h = L >> 4, l = L & 15;
    const int n = (blockIdx.x * 8 + wid) * 2 + h;
    if (n >= N_CNT) return;
    const int beg = g_ofs[n], end = g_ofs[n + 1];
    float4 acc = *(const float4*)(g_x + n * 64 + 4 * l);
    const float4 m = *(const float4*)(g_md + n * 64 + 4 * l);
    acc.x += m.x; acc.y += m.y; acc.z += m.z; acc.w += m.w;
#pragma unroll 8
    for (int i = beg; i < end; i++) {
        const int row = g_row[i];
        const float4 v = ldxh(g_xh2, row, l);
        acc.x += v.x; acc.y += v.y; acc.z += v.z; acc.w += v.w;
    }
    const float d = g_invdeg[n];
    acc.x *= d; acc.y *= d; acc.z *= d; acc.w *= d;
    const int g = batch[n];
    red4f(g_meanacc + g * 64 + 4 * l, acc.x, acc.y, acc.z, acc.w);
    unsigned* mp = g_maxacc + g * 64 + 4 * l;
    atomicMax(mp + 0, fkey(acc.x));
    atomicMax(mp + 1, fkey(acc.y));
    atomicMax(mp + 2, fkey(acc.z));
    atomicMax(mp + 3, fkey(acc.w));
    if (l == 0) atomicAdd(g_gcnt + g, 1.f);
}

// ---------------- K5: classifier ----------------
__global__ void k_cls(const float* __restrict__ CW1, const float* __restrict__ Cb1,
                      const float* __restrict__ CW2, const float* __restrict__ Cb2,
                      float* __restrict__ out) {
    __shared__ float pooled[128];
    __shared__ float hs[64];
    const int g = blockIdx.x, j = threadIdx.x;
    float mean = g_meanacc[g * 64 + j] / fmaxf(g_gcnt[g], 1.f);
    unsigned k = g_maxacc[g * 64 + j];
    float mx = (k & 0x80000000u) ? __uint_as_float(k & 0x7FFFFFFFu) : __uint_as_float(~k);
    pooled[j] = mean;
    pooled[64 + j] = mx;
    __syncthreads();
    float hv = Cb1[j];
#pragma unroll 8
    for (int k2 = 0; k2 < 128; k2++) hv += pooled[k2] * CW1[k2 * 64 + j];
    hs[j] = fmaxf(hv, 0.f);
    __syncthreads();
    if (j < 10) {
        float o = Cb2[j];
#pragma unroll
        for (int k2 = 0; k2 < 64; k2++) o += hs[k2] * CW2[k2 * 10 + j];
        out[g * 10 + j] = o;
    }
}

// ---------------- host launcher ----------------
extern "C" void kernel_launch(void* const* d_in, const int* in_sizes, int n_in,
                              void* d_out, int out_size) {
    const int* ei      = (const int*)d_in[0];
    const int* ports   = (const int*)d_in[1];
    const int* flags   = (const int*)d_in[2];
    const float* eattr = (const float*)d_in[3];
    const int* batch   = (const int*)d_in[4];
    const float* embp  = (const float*)d_in[5];
    const float* embf  = (const float*)d_in[6];
    const float* W1    = (const float*)d_in[7];
    const float* b1    = (const float*)d_in[8];
    const float* W2    = (const float*)d_in[9];
    const float* b2    = (const float*)d_in[10];
    const float* CW1   = (const float*)d_in[11];
    const float* Cb1   = (const float*)d_in[12];
    const float* CW2   = (const float*)d_in[13];
    const float* Cb2   = (const float*)d_in[14];
    float* out = (float*)d_out;

    void *p_icnt, *p_state, *p_mean, *p_max, *p_gc, *p_nctr;
    cudaGetSymbolAddress(&p_icnt, g_icnt);
    cudaGetSymbolAddress(&p_state, g_state);
    cudaGetSymbolAddress(&p_mean, g_meanacc);
    cudaGetSymbolAddress(&p_max, g_maxacc);
    cudaGetSymbolAddress(&p_gc, g_gcnt);
    cudaGetSymbolAddress(&p_nctr, g_nctr);
    cudaMemsetAsync(p_icnt, 0, sizeof(int) * N_CNT);
    cudaMemsetAsync(p_state, 0, sizeof(unsigned) * NB_SCAN);
    cudaMemsetAsync(p_mean, 0, sizeof(float) * NGRAPH * 64);
    cudaMemsetAsync(p_max, 0, sizeof(unsigned) * NGRAPH * 64);
    cudaMemsetAsync(p_gc, 0, sizeof(float) * NGRAPH);
    cudaMemsetAsync(p_nctr, 0, sizeof(int));

    k_prep<<<1056 + DEG_BLKS, 256>>>(embp, embf, W1, b1, ei);   // (1)
    k_scan<<<NB_SCAN, 1024>>>();                                // (2)
    k_fill<<<(E_CNT + 255) / 256, 256>>>(ei);                   // (3)
    k_eW<<<EW_BLKS, 256>>>(eattr, ports, flags, W1);            // (4) <- ncu capture slot
    k_gather<<<GATHER_BLKS, 256>>>(W2, b1, b2);                 // (5)
    k_spmm1<<<(N_CNT / 2 + 7) / 8, 256>>>();                    // (6)
    k_spmm_pool<<<(N_CNT / 2 + 7) / 8, 256>>>(batch);           // (7)
    k_cls<<<NGRAPH, 64>>>(CW1, Cb1, CW2, Cb2, out);             // (8)
}

// round 17
// speedup vs baseline: 1.4667x; 1.4667x over previous
#include <cuda_runtime.h>
#include <cuda_fp16.h>

typedef unsigned long long ull;

#define E_CNT 1600000
#define N_CNT 100000
#define NGRAPH 64
#define NB_SCAN ((N_CNT + 1023) / 1024)   // 98

// ---------------- device scratch ----------------
__device__ alignas(16) unsigned g_portWh[65536 * 32];  // half2[32] per port (incl b1)
__device__ alignas(16) unsigned g_flagsWh[256 * 32];   // half2[32] per flag
__device__ float g_invdeg[N_CNT];
__device__ alignas(16) float g_md[N_CNT * 64];
__device__ alignas(16) float g_x[N_CNT * 64];          // x2 fp32 (pass-1 output)
__device__ alignas(16) unsigned g_xh[N_CNT * 32];      // x1 as half2
__device__ alignas(16) unsigned g_xh2[N_CNT * 32];     // x2 as half2
__device__ float g_meanacc[NGRAPH * 64];
__device__ unsigned g_maxacc[NGRAPH * 64];
__device__ float g_gcnt[NGRAPH];
__device__ int g_nctr;                  // work-stealing cursor: gather
__device__ int g_sctr1;                 // work-stealing cursor: spmm1
__device__ int g_sctr2;                 // work-stealing cursor: spmm_pool
// CSR
__device__ int g_icnt[N_CNT];
__device__ int g_ofs[N_CNT + 1];
__device__ int g_wr[N_CNT];
__device__ unsigned g_state[NB_SCAN];
__device__ ull g_epf[E_CNT + 8];        // {hi: port*256+flag, lo: eid}
__device__ int g_row[E_CNT];

// ---------------- packed f32x2 helpers ----------------
__device__ __forceinline__ ull pack2(float x, float y) {
    ull r; asm("mov.b64 %0,{%1,%2};" : "=l"(r) : "f"(x), "f"(y)); return r;
}
__device__ __forceinline__ ull packdup(float x) {
    ull r; asm("mov.b64 %0,{%1,%1};" : "=l"(r) : "f"(x)); return r;
}
__device__ __forceinline__ void unpack2(ull v, float& x, float& y) {
    asm("mov.b64 {%0,%1},%2;" : "=f"(x), "=f"(y) : "l"(v));
}
__device__ __forceinline__ ull fma2(ull a, ull b, ull c) {
    asm("fma.rn.f32x2 %0,%1,%2,%0;" : "+l"(c) : "l"(a), "l"(b)); return c;
}
__device__ __forceinline__ ull fma2s(float s, ull b, ull c) {
    return fma2(packdup(s), b, c);
}
__device__ __forceinline__ ull add2(ull a, ull b) {
    ull d; asm("add.rn.f32x2 %0,%1,%2;" : "=l"(d) : "l"(a), "l"(b)); return d;
}
__device__ __forceinline__ ull mul2(ull a, ull b) {
    ull d; asm("mul.rn.f32x2 %0,%1,%2;" : "=l"(d) : "l"(a), "l"(b)); return d;
}
__device__ __forceinline__ void red4f(float* p, float a, float b, float c, float d) {
    asm volatile("red.global.add.v4.f32 [%0],{%1,%2,%3,%4};"
                 :: "l"(p), "f"(a), "f"(b), "f"(c), "f"(d) : "memory");
}
__device__ __forceinline__ unsigned fkey(float f) {
    unsigned u = __float_as_uint(f);
    return (u & 0x80000000u) ? ~u : (u | 0x80000000u);
}

// ---------------- K0: prep = portW + flagsW + pool-zero + degree count ----------
#define DEG_BLKS ((E_CNT / 4 + 255) / 256)
__global__ void __launch_bounds__(256) k_prep(const float* __restrict__ embp,
                                              const float* __restrict__ embf,
                                              const float* __restrict__ W1,
                                              const float* __restrict__ b1,
                                              const int* __restrict__ ei) {
    const int b = blockIdx.x;
    if (b < 1024) {
        __shared__ alignas(16) float Wp[16 * 64];
        __shared__ alignas(16) float b1s[64];
        for (int i = threadIdx.x; i < 16 * 64; i += 256) Wp[i] = W1[16 * 64 + i];
        if (threadIdx.x < 64) b1s[threadIdx.x] = b1[threadIdx.x];
        __syncthreads();
        const int wid = threadIdx.x >> 5, L = threadIdx.x & 31;
        for (int p = b * 8 + wid; p < 65536; p += 8192) {
            float a = (L < 16) ? embp[p * 16 + L] : 0.f;
            ull acc = *(const ull*)(b1s + 2 * L);
#pragma unroll
            for (int k = 0; k < 16; k++)
                acc = fma2s(__shfl_sync(0xffffffffu, a, k), *(const ull*)(Wp + k * 64 + 2 * L), acc);
            float x, y; unpack2(acc, x, y);
            __half2 h = __floats2half2_rn(x, y);
            g_portWh[p * 32 + L] = *(unsigned*)&h;
        }
    } else if (b < 1056) {
        const int idx = (b - 1024) * 256 + threadIdx.x;  // [0, 8192)
        const int r = idx >> 5, jp = idx & 31;
        const float e0 = embf[r * 2], e1 = embf[r * 2 + 1];
        const float x = e0 * W1[32 * 64 + 2 * jp] + e1 * W1[33 * 64 + 2 * jp];
        const float y = e0 * W1[32 * 64 + 2 * jp + 1] + e1 * W1[33 * 64 + 2 * jp + 1];
        __half2 h = __floats2half2_rn(x, y);
        g_flagsWh[idx] = *(unsigned*)&h;
    } else if (b == 1056) {
        // zero pool accumulators + work-stealing cursors
        for (int i = threadIdx.x; i < NGRAPH * 64; i += 256) {
            g_meanacc[i] = 0.f;
            g_maxacc[i] = 0u;
        }
        if (threadIdx.x < NGRAPH) g_gcnt[threadIdx.x] = 0.f;
        if (threadIdx.x == 64) g_nctr = 0;
        if (threadIdx.x == 65) g_sctr1 = 0;
        if (threadIdx.x == 66) g_sctr2 = 0;
    } else {
        const int i = (b - 1057) * 256 + threadIdx.x;
        if (i < E_CNT / 4) {
            int4 c = *(const int4*)(ei + E_CNT + i * 4);
            atomicAdd(g_icnt + c.x, 1);
            atomicAdd(g_icnt + c.y, 1);
            atomicAdd(g_icnt + c.z, 1);
            atomicAdd(g_icnt + c.w, 1);
        }
    }
}

// ---------------- K-scan: single-pass decoupled-lookback prefix scan ----------------
__global__ void __launch_bounds__(1024) k_scan(void) {
    __shared__ int s[1024];
    __shared__ int s_base;
    const int b = blockIdx.x, t = threadIdx.x;
    const int idx = b * 1024 + t;
    const int v = (idx < N_CNT) ? g_icnt[idx] : 0;
    s[t] = v;
    __syncthreads();
#pragma unroll
    for (int d2 = 1; d2 < 1024; d2 <<= 1) {
        int tmp = (t >= d2) ? s[t - d2] : 0;
        __syncthreads();
        s[t] += tmp;
        __syncthreads();
    }
    const int incl = s[t];
    const int total = s[1023];
    if (t == 0) {
        if (b == 0) {
            atomicExch(&g_state[0], (2u << 30) | (unsigned)total);
            s_base = 0;
        } else {
            atomicExch(&g_state[b], (1u << 30) | (unsigned)total);
            int excl = 0, j = b - 1;
            for (;;) {
                unsigned q = atomicAdd(&g_state[j], 0u);
                unsigned st = q >> 30;
                if (st == 0u) continue;
                excl += (int)(q & 0x3FFFFFFFu);
                if (st == 2u) break;
                j--;
            }
            __threadfence();
            atomicExch(&g_state[b], (2u << 30) | (unsigned)(excl + total));
            s_base = excl;
        }
    }
    __syncthreads();
    const int o = s_base + incl - v;
    if (idx < N_CNT) { g_ofs[idx] = o; g_wr[idx] = o; }
    if (idx == N_CNT - 1) g_ofs[N_CNT] = s_base + incl;
}

// ---------------- K-fill: CSR fill (SoA: epf + row) ----------------
__global__ void k_fill(const int* __restrict__ ei, const int* __restrict__ ports,
                       const int* __restrict__ flags) {
    int e = blockIdx.x * blockDim.x + threadIdx.x;
    if (e < E_CNT) {
        int col = ei[E_CNT + e];
        int p = atomicAdd(g_wr + col, 1);
        unsigned pf = ((unsigned)ports[e] << 8) | (unsigned)flags[e];
        g_epf[p] = ((ull)pf << 32) | (unsigned)e;
        g_row[p] = ei[e];
    }
}

// ---------------- K1: fused gather (edge layer-1) + node W2 GEMM ----------------
// warp per node (work-stealing); DEPTH-4 software pipeline, 3 regs/slot.
#define GATHER_BLKS 444   // 148 SMs * 3 blocks

#define PREF(idx, aV, pV, fV) do {                                          \
    const ull f_ = g_epf[idx];                                              \
    const unsigned pf_ = (unsigned)(f_ >> 32);                              \
    pV = g_portWh[(pf_ >> 8) * 32 + L];                                     \
    fV = g_flagsWh[(pf_ & 255u) * 32 + L];                                  \
    aV = eattr[(size_t)(unsigned)f_ * 16 + l16];                            \
} while (0)

#define CONSUME(aV, pV, fV) do {                                            \
    const float2 pwf_ = __half22float2(*(const __half2*)&(pV));             \
    const float2 fwf_ = __half22float2(*(const __half2*)&(fV));             \
    ull acc0_ = pack2(pwf_.x + fwf_.x, pwf_.y + fwf_.y);                    \
    ull acc1_ = 0ull;                                                       \
    _Pragma("unroll")                                                       \
    for (int k_ = 0; k_ < 16; k_ += 2) {                                    \
        acc0_ = fma2s(__shfl_sync(0xffffffffu, aV, k_, 16), Wr[k_], acc0_); \
        acc1_ = fma2s(__shfl_sync(0xffffffffu, aV, k_ + 1, 16), Wr[k_ + 1], acc1_); \
    }                                                                       \
    const ull accv_ = add2(acc0_, acc1_);                                   \
    hp = add2(hp, accv_);                                                   \
    float ax_, ay_; unpack2(accv_, ax_, ay_);                               \
    hs = add2(hs, pack2(fmaxf(ax_, 0.f), fmaxf(ay_, 0.f)));                 \
} while (0)

__global__ void __launch_bounds__(256, 3) k_gather(
    const float* __restrict__ eattr, const float* __restrict__ W1,
    const float* __restrict__ W2, const float* __restrict__ b1,
    const float* __restrict__ b2) {
    __shared__ alignas(16) float4 W2p[1024];
    __shared__ alignas(16) float b1s[64];
    __shared__ alignas(16) float b2s[64];
    for (int idx = threadIdx.x; idx < 1024; idx += 256) {
        const int kk = idx >> 5, LL = idx & 31;
        W2p[idx] = make_float4(W2[(2 * kk) * 64 + 2 * LL], W2[(2 * kk) * 64 + 2 * LL + 1],
                               W2[(2 * kk + 1) * 64 + 2 * LL], W2[(2 * kk + 1) * 64 + 2 * LL + 1]);
    }
    if (threadIdx.x < 64) { b1s[threadIdx.x] = b1[threadIdx.x]; b2s[threadIdx.x] = b2[threadIdx.x]; }
    __syncthreads();
    const int L = threadIdx.x & 31;
    const int l16 = L & 15;
    ull Wr[16];
#pragma unroll
    for (int k = 0; k < 16; k++) Wr[k] = *(const ull*)(W1 + k * 64 + 2 * L);

    int n0 = 0;
    if (L == 0) n0 = atomicAdd(&g_nctr, 4);
    n0 = __shfl_sync(0xffffffffu, n0, 0);
    while (n0 < N_CNT) {
        const int nlim = (n0 + 4 < N_CNT) ? n0 + 4 : N_CNT;
#pragma unroll 1
        for (int n = n0; n < nlim; n++) {
            const int beg = g_ofs[n], end = g_ofs[n + 1];
            const int deg = end - beg;
            ull hp = 0ull, hs = 0ull;
            if (deg > 0) {
                float a0, a1, a2, a3;
                unsigned pw0, fw0, pw1, fw1, pw2, fw2, pw3, fw3;
                PREF(beg, a0, pw0, fw0);
                {
                    const int j1 = (beg + 1 < end) ? beg + 1 : beg;
                    const int j2 = (beg + 2 < end) ? beg + 2 : beg;
                    const int j3 = (beg + 3 < end) ? beg + 3 : beg;
                    PREF(j1, a1, pw1, fw1);
                    PREF(j2, a2, pw2, fw2);
                    PREF(j3, a3, pw3, fw3);
                }
                int i = beg;
#pragma unroll 1
                for (;;) {
                    CONSUME(a0, pw0, fw0);
                    if (i + 4 < end) PREF(i + 4, a0, pw0, fw0);
                    if (++i >= end) break;
                    CONSUME(a1, pw1, fw1);
                    if (i + 4 < end) PREF(i + 4, a1, pw1, fw1);
                    if (++i >= end) break;
                    CONSUME(a2, pw2, fw2);
                    if (i + 4 < end) PREF(i + 4, a2, pw2, fw2);
                    if (++i >= end) break;
                    CONSUME(a3, pw3, fw3);
                    if (i + 4 < end) PREF(i + 4, a3, pw3, fw3);
                    if (++i >= end) break;
                }
            }
            const float cnt = (float)deg;
            const float inv = 1.f / fmaxf(cnt, 1.f);
            const float c = 1.f - cnt * inv;
            float q0, q1, s0, s1;
            unpack2(hp, q0, q1);
            unpack2(hs, s0, s1);
            const ull hh = pack2(s0 + fmaxf(q0 * inv + b1s[2 * L] * c, 0.f),
                                 s1 + fmaxf(q1 * inv + b1s[2 * L + 1] * c, 0.f));
            const float d = cnt + 1.f;
            ull m0 = pack2(b2s[2 * L] * d, b2s[2 * L + 1] * d);
            ull m1 = 0ull;
#pragma unroll
            for (int kk = 0; kk < 32; kk += 2) {
                const ull t0 = __shfl_sync(0xffffffffu, hh, kk);
                const ull t1 = __shfl_sync(0xffffffffu, hh, kk + 1);
                float x0, x1, x2, x3;
                unpack2(t0, x0, x1);
                unpack2(t1, x2, x3);
                const float4 w0 = W2p[kk * 32 + L];
                const float4 w1 = W2p[(kk + 1) * 32 + L];
                m0 = fma2s(x0, pack2(w0.x, w0.y), m0);
                m0 = fma2s(x1, pack2(w0.z, w0.w), m0);
                m1 = fma2s(x2, pack2(w1.x, w1.y), m1);
                m1 = fma2s(x3, pack2(w1.z, w1.w), m1);
            }
            const ull m = add2(m0, m1);
            const float invd = 1.f / d;
            *(ull*)(g_md + n * 64 + 2 * L) = m;
            float xv0, xv1;
            unpack2(mul2(m, packdup(invd)), xv0, xv1);
            __half2 xh = __floats2half2_rn(xv0, xv1);
            g_xh[n * 32 + L] = *(unsigned*)&xh;
            if (L == 0) g_invdeg[n] = invd;
        }
        if (L == 0) n0 = atomicAdd(&g_nctr, 4);
        n0 = __shfl_sync(0xffffffffu, n0, 0);
    }
}

// ---------------- half2-pair load: dims 4l..4l+3 of node row ----------------
__device__ __forceinline__ float4 ldxh(const unsigned* __restrict__ xh, int row, int l) {
    const ull hv = *(const ull*)(xh + row * 32 + 2 * l);
    const unsigned h0 = (unsigned)hv, h1 = (unsigned)(hv >> 32);
    const float2 f0 = __half22float2(*(const __half2*)&h0);
    const float2 f1 = __half22float2(*(const __half2*)&h1);
    return make_float4(f0.x, f0.y, f1.x, f1.y);
}

// ---------------- K3: SpMM pass 1 (work-stealing): x2 = (md*(1+invd)+Σ x1h)*invd
#define SPMM_BLKS 592   // 148 * 4
__global__ void __launch_bounds__(256) k_spmm1(void) {
    const int L = threadIdx.x & 31;
    const int h = L >> 4, l = L & 15;
    int u0 = 0;
    if (L == 0) u0 = atomicAdd(&g_sctr1, 4);
    u0 = __shfl_sync(0xffffffffu, u0, 0);
    while (u0 < N_CNT / 2) {
        const int ul = (u0 + 4 < N_CNT / 2) ? u0 + 4 : N_CNT / 2;
#pragma unroll 1
        for (int u = u0; u < ul; u++) {
            const int n = u * 2 + h;
            const int beg = g_ofs[n], end = g_ofs[n + 1];
            const float invd = g_invdeg[n];
            const float4 m = *(const float4*)(g_md + n * 64 + 4 * l);
            const float c = 1.f + invd;
            float4 acc = make_float4(m.x * c, m.y * c, m.z * c, m.w * c);
#pragma unroll 8
            for (int i = beg; i < end; i++) {
                const int row = g_row[i];
                const float4 v = ldxh(g_xh, row, l);
                acc.x += v.x; acc.y += v.y; acc.z += v.z; acc.w += v.w;
            }
            acc.x *= invd; acc.y *= invd; acc.z *= invd; acc.w *= invd;
            *(float4*)(g_x + n * 64 + 4 * l) = acc;
            __half2 ha = __floats2half2_rn(acc.x, acc.y);
            __half2 hb = __floats2half2_rn(acc.z, acc.w);
            ull hv = ((ull)(*(unsigned*)&hb) << 32) | (*(unsigned*)&ha);
            *(ull*)(g_xh2 + n * 32 + 2 * l) = hv;
        }
        if (L == 0) u0 = atomicAdd(&g_sctr1, 4);
        u0 = __shfl_sync(0xffffffffu, u0, 0);
    }
}

// ---------------- K4: SpMM pass 2 (work-stealing) fused with pooling ----------
__global__ void __launch_bounds__(256) k_spmm_pool(const int* __restrict__ batch) {
    const int L = threadIdx.x & 31;
    const int h = L >> 4, l = L & 15;
    int u0 = 0;
    if (L == 0) u0 = atomicAdd(&g_sctr2, 4);
    u0 = __shfl_sync(0xffffffffu, u0, 0);
    while (u0 < N_CNT / 2) {
        const int ul = (u0 + 4 < N_CNT / 2) ? u0 + 4 : N_CNT / 2;
#pragma unroll 1
        for (int u = u0; u < ul; u++) {
            const int n = u * 2 + h;
            const int beg = g_ofs[n], end = g_ofs[n + 1];
            float4 acc = *(const float4*)(g_x + n * 64 + 4 * l);
            const float4 m = *(const float4*)(g_md + n * 64 + 4 * l);
            acc.x += m.x; acc.y += m.y; acc.z += m.z; acc.w += m.w;
#pragma unroll 8
            for (int i = beg; i < end; i++) {
                const int row = g_row[i];
                const float4 v = ldxh(g_xh2, row, l);
                acc.x += v.x; acc.y += v.y; acc.z += v.z; acc.w += v.w;
            }
            const float d = g_invdeg[n];
            acc.x *= d; acc.y *= d; acc.z *= d; acc.w *= d;
            const int g = batch[n];
            red4f(g_meanacc + g * 64 + 4 * l, acc.x, acc.y, acc.z, acc.w);
            unsigned* mp = g_maxacc + g * 64 + 4 * l;
            atomicMax(mp + 0, fkey(acc.x));
            atomicMax(mp + 1, fkey(acc.y));
            atomicMax(mp + 2, fkey(acc.z));
            atomicMax(mp + 3, fkey(acc.w));
            if (l == 0) atomicAdd(g_gcnt + g, 1.f);
        }
        if (L == 0) u0 = atomicAdd(&g_sctr2, 4);
        u0 = __shfl_sync(0xffffffffu, u0, 0);
    }
}

// ---------------- K5: classifier ----------------
__global__ void k_cls(const float* __restrict__ CW1, const float* __restrict__ Cb1,
                      const float* __restrict__ CW2, const float* __restrict__ Cb2,
                      float* __restrict__ out) {
    __shared__ float pooled[128];
    __shared__ float hs[64];
    const int g = blockIdx.x, j = threadIdx.x;
    float mean = g_meanacc[g * 64 + j] / fmaxf(g_gcnt[g], 1.f);
    unsigned k = g_maxacc[g * 64 + j];
    float mx = (k & 0x80000000u) ? __uint_as_float(k & 0x7FFFFFFFu) : __uint_as_float(~k);
    pooled[j] = mean;
    pooled[64 + j] = mx;
    __syncthreads();
    float hv = Cb1[j];
#pragma unroll 8
    for (int k2 = 0; k2 < 128; k2++) hv += pooled[k2] * CW1[k2 * 64 + j];
    hs[j] = fmaxf(hv, 0.f);
    __syncthreads();
    if (j < 10) {
        float o = Cb2[j];
#pragma unroll
        for (int k2 = 0; k2 < 64; k2++) o += hs[k2] * CW2[k2 * 10 + j];
        out[g * 10 + j] = o;
    }
}

// ---------------- host launcher ----------------
extern "C" void kernel_launch(void* const* d_in, const int* in_sizes, int n_in,
                              void* d_out, int out_size) {
    const int* ei      = (const int*)d_in[0];
    const int* ports   = (const int*)d_in[1];
    const int* flags   = (const int*)d_in[2];
    const float* eattr = (const float*)d_in[3];
    const int* batch   = (const int*)d_in[4];
    const float* embp  = (const float*)d_in[5];
    const float* embf  = (const float*)d_in[6];
    const float* W1    = (const float*)d_in[7];
    const float* b1    = (const float*)d_in[8];
    const float* W2    = (const float*)d_in[9];
    const float* b2    = (const float*)d_in[10];
    const float* CW1   = (const float*)d_in[11];
    const float* Cb1   = (const float*)d_in[12];
    const float* CW2   = (const float*)d_in[13];
    const float* Cb2   = (const float*)d_in[14];
    float* out = (float*)d_out;

    void *p_icnt, *p_state;
    cudaGetSymbolAddress(&p_icnt, g_icnt);
    cudaGetSymbolAddress(&p_state, g_state);
    cudaMemsetAsync(p_icnt, 0, sizeof(int) * N_CNT);
    cudaMemsetAsync(p_state, 0, sizeof(unsigned) * NB_SCAN);

    k_prep<<<1057 + DEG_BLKS, 256>>>(embp, embf, W1, b1, ei);   // (1)
    k_scan<<<NB_SCAN, 1024>>>();                                // (2)
    k_fill<<<(E_CNT + 255) / 256, 256>>>(ei, ports, flags);     // (3)
    k_gather<<<GATHER_BLKS, 256>>>(eattr, W1, W2, b1, b2);      // (4) <- ncu capture slot
    k_spmm1<<<SPMM_BLKS, 256>>>();                              // (5)
    k_spmm_pool<<<SPMM_BLKS, 256>>>(batch);                     // (6)
    k_cls<<<NGRAPH, 64>>>(CW1, Cb1, CW2, Cb2, out);             // (7)
}